// round 1
// baseline (speedup 1.0000x reference)
#include <cuda_runtime.h>

#define FULL 0xffffffffu

static constexpr int B_ = 64;
static constexpr int S_ = 12;
static constexpr int N_ = 207;
static constexpr int F_ = 2;
static constexpr int NCIRC = B_ * N_;   // 13248
static constexpr int WPB = 8;           // warps (circuits) per block
static constexpr float PI_F = 3.14159265358979323846f;

// State mapping: flat index i (8 bits, qubit q <-> bit position 7-q).
// lane = bits [7:3], register r = bits [2:0]. 8 complex amps per lane.

template<int P>
__device__ __forceinline__ void apply_ry(float (&re)[8], float (&im)[8],
                                         float c, float s, int lane) {
    if constexpr (P < 3) {
        constexpr int m = 1 << P;
        #pragma unroll
        for (int r = 0; r < 8; ++r) {
            if ((r & m) == 0) {
                const int r1 = r | m;
                float a0r = re[r], a0i = im[r];
                float a1r = re[r1], a1i = im[r1];
                re[r]  = fmaf(c, a0r, -s * a1r);
                im[r]  = fmaf(c, a0i, -s * a1i);
                re[r1] = fmaf(s, a0r,  c * a1r);
                im[r1] = fmaf(s, a0i,  c * a1i);
            }
        }
    } else {
        constexpr int L = 1 << (P - 3);
        const float sgn = ((lane >> (P - 3)) & 1) ? s : -s;
        #pragma unroll
        for (int r = 0; r < 8; ++r) {
            float prr = __shfl_xor_sync(FULL, re[r], L);
            float pri = __shfl_xor_sync(FULL, im[r], L);
            re[r] = fmaf(c, re[r], sgn * prr);
            im[r] = fmaf(c, im[r], sgn * pri);
        }
    }
}

// CNOT: new[i] = old[i ^ (bit_pc(i) << PT)]. PT compile-time, pc runtime (folds
// to constant for conv-layer calls after inlining).
template<int PT>
__device__ __forceinline__ void apply_cnot(float (&re)[8], float (&im)[8],
                                           int pc, int lane) {
    if constexpr (PT < 3) {
        constexpr int m = 1 << PT;
        #pragma unroll
        for (int r = 0; r < 8; ++r) {
            if ((r & m) == 0) {
                const int r1 = r | m;
                // pc != PT, so control bit identical for both pair members
                const int bc = (((lane << 3) | r) >> pc) & 1;
                float t0r = bc ? re[r1] : re[r];
                float t1r = bc ? re[r]  : re[r1];
                float t0i = bc ? im[r1] : im[r];
                float t1i = bc ? im[r]  : im[r1];
                re[r] = t0r; re[r1] = t1r;
                im[r] = t0i; im[r1] = t1i;
            }
        }
    } else {
        constexpr int L = 1 << (PT - 3);
        #pragma unroll
        for (int r = 0; r < 8; ++r) {
            float prr = __shfl_xor_sync(FULL, re[r], L);
            float pri = __shfl_xor_sync(FULL, im[r], L);
            const int bc = (((lane << 3) | r) >> pc) & 1;
            re[r] = bc ? prr : re[r];
            im[r] = bc ? pri : im[r];
        }
    }
}

template<int Q1, int Q2>
__device__ __forceinline__ void conv_pair(float (&re)[8], float (&im)[8],
                                          const float* __restrict__ sc,
                                          const float* __restrict__ ss,
                                          int pb, int lane) {
    apply_ry<7 - Q1>(re, im, sc[pb + 0], ss[pb + 0], lane);
    apply_ry<7 - Q2>(re, im, sc[pb + 1], ss[pb + 1], lane);
    apply_cnot<7 - Q2>(re, im, 7 - Q1, lane);   // ctrl Q1, target Q2
    apply_ry<7 - Q1>(re, im, sc[pb + 2], ss[pb + 2], lane);
    apply_ry<7 - Q2>(re, im, sc[pb + 3], ss[pb + 3], lane);
    apply_cnot<7 - Q1>(re, im, 7 - Q2, lane);   // ctrl Q2, target Q1
}

__global__ __launch_bounds__(256)
void qcnn_kernel(const float* __restrict__ x, const float* __restrict__ adj,
                 const float* __restrict__ w_proj, const float* __restrict__ b_proj,
                 const float* __restrict__ qp,
                 const float* __restrict__ w1, const float* __restrict__ b1,
                 const float* __restrict__ w2, const float* __restrict__ b2,
                 const float* __restrict__ w3, const float* __restrict__ b3,
                 float* __restrict__ out) {
    __shared__ float sc[64], ss[64];       // cos/sin of q_params/2
    __shared__ float w1t[8 * 64];          // [k][row] = w1[row*8+k]
    __shared__ float w2t[64 * 32];         // [j][row] = w2[row*64+j]
    __shared__ float h1buf[WPB][64];

    const int tid = threadIdx.x;
    if (tid < 64) {
        float v = qp[tid];
        float s, c;
        sincosf(0.5f * v, &s, &c);
        sc[tid] = c; ss[tid] = s;
    }
    for (int idx = tid; idx < 512; idx += 256) {
        int row = idx >> 3, k = idx & 7;
        w1t[k * 64 + row] = w1[idx];
    }
    for (int idx = tid; idx < 2048; idx += 256) {
        int row = idx >> 6, j = idx & 63;
        w2t[j * 32 + row] = w2[idx];
    }
    __syncthreads();

    const int wid = tid >> 5;
    const int lane = tid & 31;
    const int cir = blockIdx.x * WPB + wid;
    if (cir >= NCIRC) return;              // exact fit (1656*8 == 13248)
    const int b = cir / N_;
    const int n = cir - b * N_;

    // ---- angle projection: angles[k] = clip(feats . w_proj[k] + b_proj[k]) ----
    float av = 0.f, cv = 0.f, sv = 0.f;
    if (lane < 8) {
        av = b_proj[lane];
        const float* wrow = w_proj + lane * (S_ * F_);
        const float* xb = x + (size_t)b * (S_ * N_ * F_) + n * F_;
        #pragma unroll
        for (int j = 0; j < S_ * F_; ++j) {
            int s = j >> 1, f = j & 1;
            av = fmaf(wrow[j], xb[s * (N_ * F_) + f], av);
        }
        av = fminf(fmaxf(av, -PI_F), PI_F);
        sincosf(0.5f * av, &sv, &cv);
    }
    float ch[8], sh[8], aa[8];
    #pragma unroll
    for (int q = 0; q < 8; ++q) {
        ch[q] = __shfl_sync(FULL, cv, q);
        sh[q] = __shfl_sync(FULL, sv, q);
        aa[q] = __shfl_sync(FULL, av, q);
    }

    // ---- initial product state (RY on all qubits) with RZ(a[4..7]) phases ----
    // lane bit k <-> flat position 3+k <-> qubit 4-k
    float magLane = 1.f;
    magLane *= ((lane >> 0) & 1) ? sh[4] : ch[4];
    magLane *= ((lane >> 1) & 1) ? sh[3] : ch[3];
    magLane *= ((lane >> 2) & 1) ? sh[2] : ch[2];
    magLane *= ((lane >> 3) & 1) ? sh[1] : ch[1];
    magLane *= ((lane >> 4) & 1) ? sh[0] : ch[0];
    // RZ(a[4+qi]) on qubit qi: phase -a/2 for bit 0, +a/2 for bit 1 (lane bit 4-qi)
    float ph = 0.f;
    ph += (((lane >> 4) & 1) ? 0.5f : -0.5f) * aa[4];
    ph += (((lane >> 3) & 1) ? 0.5f : -0.5f) * aa[5];
    ph += (((lane >> 2) & 1) ? 0.5f : -0.5f) * aa[6];
    ph += (((lane >> 1) & 1) ? 0.5f : -0.5f) * aa[7];
    float cph, sph;
    sincosf(ph, &sph, &cph);

    float re[8], im[8];
    #pragma unroll
    for (int r = 0; r < 8; ++r) {
        float m = magLane;
        m *= (r & 4) ? sh[5] : ch[5];   // bit pos 2 -> qubit 5
        m *= (r & 2) ? sh[6] : ch[6];   // bit pos 1 -> qubit 6
        m *= (r & 1) ? sh[7] : ch[7];   // bit pos 0 -> qubit 7
        re[r] = m * cph;
        im[r] = m * sph;
    }

    // ---- graph CNOT permutation: ctrl c = n%8, targets t where adj[c][t]>0, t!=c ----
    const int c = n & 7;
    int cond = 0;
    if (lane < 8) {
        float avj = adj[c * N_ + lane];
        cond = (avj > 0.f) && (lane != c);
    }
    const unsigned mask = __ballot_sync(FULL, cond);
    const int pc = 7 - c;
    if (mask & 1u)   apply_cnot<7>(re, im, pc, lane);  // t=0
    if (mask & 2u)   apply_cnot<6>(re, im, pc, lane);  // t=1
    if (mask & 4u)   apply_cnot<5>(re, im, pc, lane);  // t=2
    if (mask & 8u)   apply_cnot<4>(re, im, pc, lane);  // t=3
    if (mask & 16u)  apply_cnot<3>(re, im, pc, lane);  // t=4
    if (mask & 32u)  apply_cnot<2>(re, im, pc, lane);  // t=5
    if (mask & 64u)  apply_cnot<1>(re, im, pc, lane);  // t=6
    if (mask & 128u) apply_cnot<0>(re, im, pc, lane);  // t=7

    // ---- 2 conv layers (28 params each) ----
    #pragma unroll
    for (int l = 0; l < 2; ++l) {
        const int base = l * 28;
        conv_pair<0, 1>(re, im, sc, ss, base + 0,  lane);
        conv_pair<2, 3>(re, im, sc, ss, base + 4,  lane);
        conv_pair<4, 5>(re, im, sc, ss, base + 8,  lane);
        conv_pair<6, 7>(re, im, sc, ss, base + 12, lane);
        conv_pair<1, 2>(re, im, sc, ss, base + 16, lane);
        conv_pair<3, 4>(re, im, sc, ss, base + 20, lane);
        conv_pair<5, 6>(re, im, sc, ss, base + 24, lane);
    }

    // ---- pooling: RY(qp[56+q]) on q = 0,2,4,6 ----
    apply_ry<7>(re, im, sc[56], ss[56], lane);
    apply_ry<5>(re, im, sc[58], ss[58], lane);
    apply_ry<3>(re, im, sc[60], ss[60], lane);
    apply_ry<1>(re, im, sc[62], ss[62], lane);

    // ---- <Z_w> measurement ----
    float pr[8];
    float tot = 0.f;
    #pragma unroll
    for (int r = 0; r < 8; ++r) {
        pr[r] = re[r] * re[r] + im[r] * im[r];
        tot += pr[r];
    }
    float z[8];
    #pragma unroll
    for (int w = 0; w < 5; ++w)            // qubits 0..4 live in lane bits
        z[w] = ((lane >> (4 - w)) & 1) ? -tot : tot;
    z[5] = z[6] = z[7] = 0.f;
    #pragma unroll
    for (int r = 0; r < 8; ++r) {
        z[5] += (r & 4) ? -pr[r] : pr[r];
        z[6] += (r & 2) ? -pr[r] : pr[r];
        z[7] += (r & 1) ? -pr[r] : pr[r];
    }
    #pragma unroll
    for (int off = 16; off > 0; off >>= 1) {
        #pragma unroll
        for (int w = 0; w < 8; ++w)
            z[w] += __shfl_xor_sync(FULL, z[w], off);
    }

    // ---- MLP head: 8 -> 64 -> 32 -> 1 ----
    float h1a = b1[lane];
    float h1b = b1[lane + 32];
    #pragma unroll
    for (int k = 0; k < 8; ++k) {
        h1a = fmaf(w1t[k * 64 + lane],      z[k], h1a);
        h1b = fmaf(w1t[k * 64 + lane + 32], z[k], h1b);
    }
    h1buf[wid][lane]      = fmaxf(h1a, 0.f);
    h1buf[wid][lane + 32] = fmaxf(h1b, 0.f);
    __syncwarp();

    float h2 = b2[lane];
    #pragma unroll
    for (int j = 0; j < 64; ++j)
        h2 = fmaf(w2t[j * 32 + lane], h1buf[wid][j], h2);
    h2 = fmaxf(h2, 0.f);

    float o = w3[lane] * h2;
    #pragma unroll
    for (int off = 16; off > 0; off >>= 1)
        o += __shfl_xor_sync(FULL, o, off);
    if (lane == 0) out[cir] = o + b3[0];
}

extern "C" void kernel_launch(void* const* d_in, const int* in_sizes, int n_in,
                              void* d_out, int out_size) {
    const float* x      = (const float*)d_in[0];
    const float* adj    = (const float*)d_in[1];
    const float* w_proj = (const float*)d_in[2];
    const float* b_proj = (const float*)d_in[3];
    const float* qp     = (const float*)d_in[4];
    const float* w1     = (const float*)d_in[5];
    const float* b1     = (const float*)d_in[6];
    const float* w2     = (const float*)d_in[7];
    const float* b2     = (const float*)d_in[8];
    const float* w3     = (const float*)d_in[9];
    const float* b3     = (const float*)d_in[10];
    float* out = (float*)d_out;

    const int blocks = (NCIRC + WPB - 1) / WPB;   // 1656
    qcnn_kernel<<<blocks, 256>>>(x, adj, w_proj, b_proj, qp,
                                 w1, b1, w2, b2, w3, b3, out);
}

// round 2
// speedup vs baseline: 1.5944x; 1.5944x over previous
#include <cuda_runtime.h>

#define FULL 0xffffffffu

static constexpr int B_ = 64;
static constexpr int S_ = 12;
static constexpr int N_ = 207;
static constexpr int F_ = 2;
static constexpr int NCIRC = B_ * N_;   // 13248
static constexpr int WPB = 8;
static constexpr float PI_F = 3.14159265358979323846f;

// Internal layout: flat index j = (lane<<3) | r (lane 5 bits, reg 3 bits).
// qubit -> bit position of j:  posOf = {7,6,2,1,0,5,4,3}
//   lane bit 4 = q0, b3 = q1, b2 = q5, b1 = q6, b0 = q7
//   reg  bit 2 = q2, bit 1 = q3, bit 0 = q4

__device__ __forceinline__ float shx(float v, int m) { return __shfl_xor_sync(FULL, v, m); }

// ---- RY on a register bit P ----
template<int P>
__device__ __forceinline__ void ry_reg(float (&re)[8], float (&im)[8], float c, float s) {
    constexpr int m = 1 << P;
    #pragma unroll
    for (int r = 0; r < 8; ++r) if (!(r & m)) {
        const int r1 = r | m;
        float a0r = re[r], a0i = im[r], a1r = re[r1], a1i = im[r1];
        re[r]  = fmaf(c, a0r, -s * a1r);  im[r]  = fmaf(c, a0i, -s * a1i);
        re[r1] = fmaf(s, a0r,  c * a1r);  im[r1] = fmaf(s, a0i,  c * a1i);
    }
}

// ---- RY on a lane bit LB ----
template<int LB>
__device__ __forceinline__ void ry_lane(float (&re)[8], float (&im)[8], float c, float s, int lane) {
    constexpr int L = 1 << LB;
    const float sg = ((lane >> LB) & 1) ? s : -s;
    #pragma unroll
    for (int r = 0; r < 8; ++r) {
        float pr = shx(re[r], L), pi = shx(im[r], L);
        re[r] = fmaf(c, re[r], sg * pr);
        im[r] = fmaf(c, im[r], sg * pi);
    }
}

// ---- fused conv pair, q1 at reg bit PA, q2 at reg bit PB ----
template<int PA, int PB>
__device__ __forceinline__ void conv_rr(float (&re)[8], float (&im)[8], const float* __restrict__ U) {
    float u[16];
    #pragma unroll
    for (int k = 0; k < 16; ++k) u[k] = U[k];
    constexpr int ma = 1 << PA, mb = 1 << PB;
    #pragma unroll
    for (int r0 = 0; r0 < 8; ++r0) if (!(r0 & (ma | mb))) {
        const int g1 = r0 | mb, g2 = r0 | ma, g3 = r0 | ma | mb;
        float v0 = re[r0], v1 = re[g1], v2 = re[g2], v3 = re[g3];
        re[r0] = fmaf(u[0],  v0, fmaf(u[1],  v1, fmaf(u[2],  v2, u[3]  * v3)));
        re[g1] = fmaf(u[4],  v0, fmaf(u[5],  v1, fmaf(u[6],  v2, u[7]  * v3)));
        re[g2] = fmaf(u[8],  v0, fmaf(u[9],  v1, fmaf(u[10], v2, u[11] * v3)));
        re[g3] = fmaf(u[12], v0, fmaf(u[13], v1, fmaf(u[14], v2, u[15] * v3)));
        v0 = im[r0]; v1 = im[g1]; v2 = im[g2]; v3 = im[g3];
        im[r0] = fmaf(u[0],  v0, fmaf(u[1],  v1, fmaf(u[2],  v2, u[3]  * v3)));
        im[g1] = fmaf(u[4],  v0, fmaf(u[5],  v1, fmaf(u[6],  v2, u[7]  * v3)));
        im[g2] = fmaf(u[8],  v0, fmaf(u[9],  v1, fmaf(u[10], v2, u[11] * v3)));
        im[g3] = fmaf(u[12], v0, fmaf(u[13], v1, fmaf(u[14], v2, u[15] * v3)));
    }
}

// ---- fused conv pair, q1 at lane bit LA, q2 at lane bit LB2 ----
template<int LA, int LB2>
__device__ __forceinline__ void conv_ll(float (&re)[8], float (&im)[8],
                                        const float* __restrict__ U, int lane) {
    constexpr int Ma = 1 << LA, Mb = 1 << LB2;
    const int a = (lane >> LA) & 1, b = (lane >> LB2) & 1;
    const int row = 2 * a + b;
    const float* ur = U + row * 4;
    const float wO = ur[row], wA = ur[row ^ 2], wB = ur[row ^ 1], wAB = ur[row ^ 3];
    #pragma unroll
    for (int r = 0; r < 8; ++r) {
        float pa = shx(re[r], Ma), pb = shx(re[r], Mb), pab = shx(re[r], Ma | Mb);
        re[r] = fmaf(wO, re[r], fmaf(wA, pa, fmaf(wB, pb, wAB * pab)));
        pa = shx(im[r], Ma); pb = shx(im[r], Mb); pab = shx(im[r], Ma | Mb);
        im[r] = fmaf(wO, im[r], fmaf(wA, pa, fmaf(wB, pb, wAB * pab)));
    }
}

// ---- fused conv pair, one qubit on lane bit LB, one on reg bit PB.
// LQ1 = true: q1 is the lane qubit; false: q2 is the lane qubit.
template<int LB, int PB, bool LQ1>
__device__ __forceinline__ void conv_mx(float (&re)[8], float (&im)[8],
                                        const float* __restrict__ U, int lane) {
    constexpr int Lm = 1 << LB, mb = 1 << PB;
    const int a = (lane >> LB) & 1;
    const int r0i = LQ1 ? 2 * a     : a;         // b-index of (laneBit=a, regBit=0)
    const int r1i = LQ1 ? 2 * a + 1 : 2 + a;     // (a, 1)
    const int cR0 = LQ1 ? 2 * (a ^ 1)     : (a ^ 1);
    const int cR1 = LQ1 ? 2 * (a ^ 1) + 1 : 2 + (a ^ 1);
    const float u00 = U[r0i * 4 + r0i], u01 = U[r0i * 4 + r1i],
                u02 = U[r0i * 4 + cR0], u03 = U[r0i * 4 + cR1];
    const float u10 = U[r1i * 4 + r0i], u11 = U[r1i * 4 + r1i],
                u12 = U[r1i * 4 + cR0], u13 = U[r1i * 4 + cR1];
    float pre[8], pim[8];
    #pragma unroll
    for (int r = 0; r < 8; ++r) { pre[r] = shx(re[r], Lm); pim[r] = shx(im[r], Lm); }
    #pragma unroll
    for (int r = 0; r < 8; ++r) if (!(r & mb)) {
        const int r1 = r | mb;
        float o0 = re[r], o1 = re[r1], q0 = pre[r], q1 = pre[r1];
        re[r]  = fmaf(u00, o0, fmaf(u01, o1, fmaf(u02, q0, u03 * q1)));
        re[r1] = fmaf(u10, o0, fmaf(u11, o1, fmaf(u12, q0, u13 * q1)));
        o0 = im[r]; o1 = im[r1]; q0 = pim[r]; q1 = pim[r1];
        im[r]  = fmaf(u00, o0, fmaf(u01, o1, fmaf(u02, q0, u03 * q1)));
        im[r1] = fmaf(u10, o0, fmaf(u11, o1, fmaf(u12, q0, u13 * q1)));
    }
}

__global__ __launch_bounds__(256)
void qcnn_kernel(const float* __restrict__ x, const float* __restrict__ adj,
                 const float* __restrict__ w_proj, const float* __restrict__ b_proj,
                 const float* __restrict__ qp,
                 const float* __restrict__ w1, const float* __restrict__ b1,
                 const float* __restrict__ w2, const float* __restrict__ b2,
                 const float* __restrict__ w3, const float* __restrict__ b3,
                 float* __restrict__ out) {
    __shared__ float UU[14][16];           // fused conv 4x4 matrices
    __shared__ float poolc[4], pools[4];   // pooling cos/sin (q0,2,4,6)
    __shared__ float w1t[8 * 64];
    __shared__ float w2t[64 * 32];
    __shared__ float h1buf[WPB][64];

    const int tid = threadIdx.x;

    // ---- build fused conv matrices U = C2 * G2 * C1 * G1 (basis b = 2*q1 + q2) ----
    if (tid < 14) {
        const int layer = tid / 7, pi = tid - 7 * layer;
        const int base = layer * 28 + pi * 4;
        float c0, s0, c1, s1, c2, s2, c3, s3;
        sincosf(0.5f * qp[base + 0], &s0, &c0);
        sincosf(0.5f * qp[base + 1], &s1, &c1);
        sincosf(0.5f * qp[base + 2], &s2, &c2);
        sincosf(0.5f * qp[base + 3], &s3, &c3);
        float R0[2][2] = {{c0, -s0}, {s0, c0}};
        float R1[2][2] = {{c1, -s1}, {s1, c1}};
        float R2[2][2] = {{c2, -s2}, {s2, c2}};
        float R3[2][2] = {{c3, -s3}, {s3, c3}};
        float A[4][4], G2m[4][4], Bm[4][4], Cm[4][4];
        #pragma unroll
        for (int ap = 0; ap < 2; ++ap)
        #pragma unroll
        for (int bp = 0; bp < 2; ++bp)
        #pragma unroll
        for (int aq = 0; aq < 2; ++aq)
        #pragma unroll
        for (int bq = 0; bq < 2; ++bq) {
            A[2 * ap + bp][2 * aq + bq]   = R0[ap][aq] * R1[bp][bq];
            G2m[2 * ap + bp][2 * aq + bq] = R2[ap][aq] * R3[bp][bq];
        }
        const int sig1[4] = {0, 1, 3, 2};   // CNOT q1->q2
        const int sig2[4] = {0, 3, 2, 1};   // CNOT q2->q1
        #pragma unroll
        for (int xr = 0; xr < 4; ++xr)
            #pragma unroll
            for (int m = 0; m < 4; ++m) Bm[xr][m] = A[sig1[xr]][m];
        #pragma unroll
        for (int xr = 0; xr < 4; ++xr)
            #pragma unroll
            for (int m = 0; m < 4; ++m) {
                float acc = 0.f;
                #pragma unroll
                for (int y = 0; y < 4; ++y) acc = fmaf(G2m[xr][y], Bm[y][m], acc);
                Cm[xr][m] = acc;
            }
        #pragma unroll
        for (int xr = 0; xr < 4; ++xr)
            #pragma unroll
            for (int m = 0; m < 4; ++m) UU[tid][xr * 4 + m] = Cm[sig2[xr]][m];
    }
    if (tid >= 32 && tid < 36) {
        float s, c;
        sincosf(0.5f * qp[56 + 2 * (tid - 32)], &s, &c);
        poolc[tid - 32] = c; pools[tid - 32] = s;
    }
    for (int idx = tid; idx < 512; idx += 256) {
        int row = idx >> 3, k = idx & 7;
        w1t[k * 64 + row] = w1[idx];
    }
    for (int idx = tid; idx < 2048; idx += 256) {
        int row = idx >> 6, j = idx & 63;
        w2t[j * 32 + row] = w2[idx];
    }
    __syncthreads();

    const int wid = tid >> 5;
    const int lane = tid & 31;
    const int cir = blockIdx.x * WPB + wid;
    if (cir >= NCIRC) return;
    const int b = cir / N_;
    const int n = cir - b * N_;

    // ---- angle projection ----
    float cv = 0.f, sv = 0.f;
    if (lane < 8) {
        float av = b_proj[lane];
        const float* wrow = w_proj + lane * (S_ * F_);
        const float* xb = x + (size_t)b * (S_ * N_ * F_) + n * F_;
        #pragma unroll
        for (int j = 0; j < S_ * F_; ++j) {
            int s = j >> 1, f = j & 1;
            av = fmaf(wrow[j], xb[s * (N_ * F_) + f], av);
        }
        av = fminf(fmaxf(av, -PI_F), PI_F);
        sincosf(0.5f * av, &sv, &cv);
    }
    float ch[8], sh[8];
    #pragma unroll
    for (int q = 0; q < 8; ++q) {
        ch[q] = __shfl_sync(FULL, cv, q);
        sh[q] = __shfl_sync(FULL, sv, q);
    }

    // ---- initial product state + RZ phases ----
    float magL = ((lane >> 4) & 1) ? sh[0] : ch[0];
    magL *= ((lane >> 3) & 1) ? sh[1] : ch[1];
    magL *= ((lane >> 2) & 1) ? sh[5] : ch[5];
    magL *= ((lane >> 1) & 1) ? sh[6] : ch[6];
    magL *= (lane & 1)        ? sh[7] : ch[7];
    // lane phase factor: RZ(a4) on q0 (lane b4), RZ(a5) on q1 (lane b3)
    float p0 = ((lane >> 4) & 1) ? sh[4] : -sh[4];
    float p1 = ((lane >> 3) & 1) ? sh[5] : -sh[5];
    float fr = fmaf(ch[4], ch[5], -p0 * p1);
    float fi = fmaf(ch[4], p1, p0 * ch[5]);
    // reg phase combos: RZ(a6) on q2 (reg bit2), RZ(a7) on q3 (reg bit1)
    float hr[4], hi[4];
    #pragma unroll
    for (int k = 0; k < 4; ++k) {
        float t2 = (k & 2) ? sh[6] : -sh[6];
        float t3 = (k & 1) ? sh[7] : -sh[7];
        float gr = fmaf(ch[6], ch[7], -t2 * t3);
        float gi = fmaf(ch[6], t3, t2 * ch[7]);
        hr[k] = fmaf(fr, gr, -fi * gi);
        hi[k] = fmaf(fr, gi, fi * gr);
    }
    float re[8], im[8];
    #pragma unroll
    for (int r = 0; r < 8; ++r) {
        float m = magL;
        m *= (r & 4) ? sh[2] : ch[2];   // q2
        m *= (r & 2) ? sh[3] : ch[3];   // q3
        m *= (r & 1) ? sh[4] : ch[4];   // q4
        const int k = (r >> 1) & 3;
        re[r] = m * hr[k];
        im[r] = m * hi[k];
    }

    // ---- graph CNOTs composed into one conditional XOR permutation ----
    const int c = n & 7;
    const int pcq = (0x34501267u >> (4 * c)) & 0xF;   // posOf[c]
    int cond = 0;
    if (lane < 8) cond = (adj[c * N_ + lane] > 0.f) && (lane != c);
    const unsigned bmask = __ballot_sync(FULL, cond) & 0xFFu;
    constexpr int posOf[8] = {7, 6, 2, 1, 0, 5, 4, 3};
    int M = 0;
    #pragma unroll
    for (int t = 0; t < 8; ++t) M |= (int)((bmask >> t) & 1u) << posOf[t];

    if (M) {
        const int ML = M >> 3, MR = M & 7;
        float tr[8], ti[8];
        #pragma unroll
        for (int r = 0; r < 8; ++r) {
            const int bc = (((lane << 3) | r) >> pcq) & 1;
            const int src = bc ? (lane ^ ML) : lane;
            tr[r] = __shfl_sync(FULL, re[r], src);
            ti[r] = __shfl_sync(FULL, im[r], src);
        }
        #define GCASE(K) case K: {                                        \
            _Pragma("unroll")                                             \
            for (int r = 0; r < 8; ++r) {                                 \
                const int bc = (((lane << 3) | r) >> pcq) & 1;            \
                re[r] = bc ? tr[r ^ K] : tr[r];                           \
                im[r] = bc ? ti[r ^ K] : ti[r];                           \
            } } break;
        switch (MR) {
            GCASE(0) GCASE(1) GCASE(2) GCASE(3)
            GCASE(4) GCASE(5) GCASE(6) GCASE(7)
        }
        #undef GCASE
    }

    // ---- 2 conv layers, fused 4x4 per pair ----
    #pragma unroll
    for (int l = 0; l < 2; ++l) {
        const float* Ub = &UU[l * 7][0];
        conv_ll<4, 3>(re, im, Ub + 0 * 16, lane);           // (q0,q1)
        conv_rr<2, 1>(re, im, Ub + 1 * 16);                 // (q2,q3)
        conv_mx<2, 0, false>(re, im, Ub + 2 * 16, lane);    // (q4,q5): q2 on lane
        conv_ll<1, 0>(re, im, Ub + 3 * 16, lane);           // (q6,q7)
        conv_mx<3, 2, true>(re, im, Ub + 4 * 16, lane);     // (q1,q2): q1 on lane
        conv_rr<1, 0>(re, im, Ub + 5 * 16);                 // (q3,q4)
        conv_ll<2, 1>(re, im, Ub + 6 * 16, lane);           // (q5,q6)
    }

    // ---- pooling RY on q0, q2, q4, q6 ----
    ry_lane<4>(re, im, poolc[0], pools[0], lane);  // q0
    ry_reg<2>(re, im, poolc[1], pools[1]);         // q2
    ry_reg<0>(re, im, poolc[2], pools[2]);         // q4
    ry_lane<1>(re, im, poolc[3], pools[3], lane);  // q6

    // ---- <Z_w> measurement ----
    float pr[8], tot = 0.f, z2 = 0.f, z3 = 0.f, z4 = 0.f;
    #pragma unroll
    for (int r = 0; r < 8; ++r) {
        pr[r] = fmaf(re[r], re[r], im[r] * im[r]);
        tot += pr[r];
        z2 += (r & 4) ? -pr[r] : pr[r];
        z3 += (r & 2) ? -pr[r] : pr[r];
        z4 += (r & 1) ? -pr[r] : pr[r];
    }
    float z[8];
    z[0] = ((lane >> 4) & 1) ? -tot : tot;
    z[1] = ((lane >> 3) & 1) ? -tot : tot;
    z[5] = ((lane >> 2) & 1) ? -tot : tot;
    z[6] = ((lane >> 1) & 1) ? -tot : tot;
    z[7] = (lane & 1)        ? -tot : tot;
    z[2] = z2; z[3] = z3; z[4] = z4;
    #pragma unroll
    for (int off = 16; off > 0; off >>= 1) {
        #pragma unroll
        for (int w = 0; w < 8; ++w) z[w] += shx(z[w], off);
    }

    // ---- MLP head: 8 -> 64 -> 32 -> 1 ----
    float h1a = b1[lane];
    float h1b = b1[lane + 32];
    #pragma unroll
    for (int k = 0; k < 8; ++k) {
        h1a = fmaf(w1t[k * 64 + lane],      z[k], h1a);
        h1b = fmaf(w1t[k * 64 + lane + 32], z[k], h1b);
    }
    h1buf[wid][lane]      = fmaxf(h1a, 0.f);
    h1buf[wid][lane + 32] = fmaxf(h1b, 0.f);
    __syncwarp();

    float h2 = b2[lane];
    #pragma unroll
    for (int j = 0; j < 64; ++j)
        h2 = fmaf(w2t[j * 32 + lane], h1buf[wid][j], h2);
    h2 = fmaxf(h2, 0.f);

    float o = w3[lane] * h2;
    #pragma unroll
    for (int off = 16; off > 0; off >>= 1)
        o += shx(o, off);
    if (lane == 0) out[cir] = o + b3[0];
}

extern "C" void kernel_launch(void* const* d_in, const int* in_sizes, int n_in,
                              void* d_out, int out_size) {
    const float* x      = (const float*)d_in[0];
    const float* adj    = (const float*)d_in[1];
    const float* w_proj = (const float*)d_in[2];
    const float* b_proj = (const float*)d_in[3];
    const float* qp     = (const float*)d_in[4];
    const float* w1     = (const float*)d_in[5];
    const float* b1     = (const float*)d_in[6];
    const float* w2     = (const float*)d_in[7];
    const float* b2     = (const float*)d_in[8];
    const float* w3     = (const float*)d_in[9];
    const float* b3     = (const float*)d_in[10];
    float* out = (float*)d_out;

    const int blocks = (NCIRC + WPB - 1) / WPB;   // 1656
    qcnn_kernel<<<blocks, 256>>>(x, adj, w_proj, b_proj, qp,
                                 w1, b1, w2, b2, w3, b3, out);
}

// round 3
// speedup vs baseline: 1.7613x; 1.1047x over previous
#include <cuda_runtime.h>

#define FULL 0xffffffffu

static constexpr int B_ = 64;
static constexpr int S_ = 12;
static constexpr int N_ = 207;
static constexpr int F_ = 2;
static constexpr int NCIRC = B_ * N_;       // 13248
static constexpr int CPB = 16;              // circuits per block (4 warps * 4)
static constexpr float PI_F = 3.14159265358979323846f;

// Layout: flat j (8 bits) = (g << 5) | r;  g = lane & 7 (3 bits), r = reg idx (5 bits)
// qubit -> j-bit:  q0->7  q1->4  q2->3  q3->2  q4->6  q5->1  q6->0  q7->5
// lane qubits {0,4,7}: g bit2=q0, bit1=q4, bit0=q7. reg qubits {1,2,3,5,6}.

__device__ __forceinline__ float shx(float v, int m) { return __shfl_xor_sync(FULL, v, m); }

// ---- RY on a register bit P ----
template<int P>
__device__ __forceinline__ void ry_reg(float (&re)[32], float (&im)[32], float c, float s) {
    constexpr int m = 1 << P;
    #pragma unroll
    for (int r = 0; r < 32; ++r) if (!(r & m)) {
        const int r1 = r | m;
        float a0r = re[r], a0i = im[r], a1r = re[r1], a1i = im[r1];
        re[r]  = fmaf(c, a0r, -s * a1r);  im[r]  = fmaf(c, a0i, -s * a1i);
        re[r1] = fmaf(s, a0r,  c * a1r);  im[r1] = fmaf(s, a0i,  c * a1i);
    }
}

// ---- RY on a lane bit LB (xor mask stays inside the 8-lane group) ----
template<int LB>
__device__ __forceinline__ void ry_lane(float (&re)[32], float (&im)[32], float c, float s, int lane) {
    constexpr int L = 1 << LB;
    const float sg = ((lane >> LB) & 1) ? s : -s;
    #pragma unroll
    for (int r = 0; r < 32; ++r) {
        float pr = shx(re[r], L), pi = shx(im[r], L);
        re[r] = fmaf(c, re[r], sg * pr);
        im[r] = fmaf(c, im[r], sg * pi);
    }
}

// ---- fused conv pair, both qubits on reg bits (PA = first qubit, PB = second) ----
template<int PA, int PB>
__device__ __forceinline__ void conv_rr(float (&re)[32], float (&im)[32], const float4* __restrict__ U4) {
    const float4 a0 = U4[0], a1 = U4[1], a2 = U4[2], a3 = U4[3];
    constexpr int ma = 1 << PA, mb = 1 << PB;
    #pragma unroll
    for (int r0 = 0; r0 < 32; ++r0) if (!(r0 & (ma | mb))) {
        const int i1 = r0 | mb, i2 = r0 | ma, i3 = r0 | ma | mb;
        float v0 = re[r0], v1 = re[i1], v2 = re[i2], v3 = re[i3];
        re[r0] = fmaf(a0.x, v0, fmaf(a0.y, v1, fmaf(a0.z, v2, a0.w * v3)));
        re[i1] = fmaf(a1.x, v0, fmaf(a1.y, v1, fmaf(a1.z, v2, a1.w * v3)));
        re[i2] = fmaf(a2.x, v0, fmaf(a2.y, v1, fmaf(a2.z, v2, a2.w * v3)));
        re[i3] = fmaf(a3.x, v0, fmaf(a3.y, v1, fmaf(a3.z, v2, a3.w * v3)));
        v0 = im[r0]; v1 = im[i1]; v2 = im[i2]; v3 = im[i3];
        im[r0] = fmaf(a0.x, v0, fmaf(a0.y, v1, fmaf(a0.z, v2, a0.w * v3)));
        im[i1] = fmaf(a1.x, v0, fmaf(a1.y, v1, fmaf(a1.z, v2, a1.w * v3)));
        im[i2] = fmaf(a2.x, v0, fmaf(a2.y, v1, fmaf(a2.z, v2, a2.w * v3)));
        im[i3] = fmaf(a3.x, v0, fmaf(a3.y, v1, fmaf(a3.z, v2, a3.w * v3)));
    }
}

// ---- fused conv pair, one qubit on lane bit LBIT, one on reg bit PB.
// LQ1 = true: lane qubit is the FIRST of the pair (basis 2*first+second).
template<int LBIT, int PB, bool LQ1>
__device__ __forceinline__ void conv_mx(float (&re)[32], float (&im)[32],
                                        const float4* __restrict__ U4, int lane) {
    constexpr int Lm = 1 << LBIT, mb = 1 << PB;
    const int a = (lane >> LBIT) & 1;
    float4 u0, u1;
    if (LQ1) { u0 = U4[2 * a]; u1 = U4[2 * a + 1]; }
    else     { u0 = U4[a];     u1 = U4[2 + a]; }
    float u00, u01, u02, u03, u10, u11, u12, u13;
    if (LQ1) {
        u00 = a ? u0.z : u0.x;  u01 = a ? u0.w : u0.y;
        u02 = a ? u0.x : u0.z;  u03 = a ? u0.y : u0.w;
        u10 = a ? u1.z : u1.x;  u11 = a ? u1.w : u1.y;
        u12 = a ? u1.x : u1.z;  u13 = a ? u1.y : u1.w;
    } else {
        u00 = a ? u0.y : u0.x;  u01 = a ? u0.w : u0.z;
        u02 = a ? u0.x : u0.y;  u03 = a ? u0.z : u0.w;
        u10 = a ? u1.y : u1.x;  u11 = a ? u1.w : u1.z;
        u12 = a ? u1.x : u1.y;  u13 = a ? u1.z : u1.w;
    }
    #pragma unroll
    for (int r0 = 0; r0 < 32; ++r0) if (!(r0 & mb)) {
        const int r1 = r0 | mb;
        float p0 = shx(re[r0], Lm), p1 = shx(re[r1], Lm);
        float o0 = re[r0], o1 = re[r1];
        re[r0] = fmaf(u00, o0, fmaf(u01, o1, fmaf(u02, p0, u03 * p1)));
        re[r1] = fmaf(u10, o0, fmaf(u11, o1, fmaf(u12, p0, u13 * p1)));
        p0 = shx(im[r0], Lm); p1 = shx(im[r1], Lm);
        o0 = im[r0]; o1 = im[r1];
        im[r0] = fmaf(u00, o0, fmaf(u01, o1, fmaf(u02, p0, u03 * p1)));
        im[r1] = fmaf(u10, o0, fmaf(u11, o1, fmaf(u12, p0, u13 * p1)));
    }
}

__global__ __launch_bounds__(128, 4)
void qcnn_kernel(const float* __restrict__ x, const float* __restrict__ adj,
                 const float* __restrict__ w_proj, const float* __restrict__ b_proj,
                 const float* __restrict__ qp,
                 const float* __restrict__ w1, const float* __restrict__ b1,
                 const float* __restrict__ w2, const float* __restrict__ b2,
                 const float* __restrict__ w3, const float* __restrict__ b3,
                 float* __restrict__ out) {
    __shared__ alignas(16) float UUs[14][16];      // fused conv 4x4 matrices
    __shared__ float poolc[4], pools[4];
    __shared__ alignas(16) float w1s[512];         // w1 natural [64][8]
    __shared__ float4 w2p4[32 * 17];               // w2 rows padded to 68 floats
    __shared__ float4 h1buf4[CPB * 17];            // h1 per circuit, padded 68
    __shared__ float b1s[64], b2s[32], w3s[32];
    __shared__ float b3s;

    const int tid = threadIdx.x;

    // ---- build fused conv matrices U = C2 * G2 * C1 * G1 ----
    if (tid < 14) {
        const int layer = tid / 7, pi = tid - 7 * layer;
        const int base = layer * 28 + pi * 4;
        float c0, s0, c1, s1, c2, s2, c3, s3;
        sincosf(0.5f * qp[base + 0], &s0, &c0);
        sincosf(0.5f * qp[base + 1], &s1, &c1);
        sincosf(0.5f * qp[base + 2], &s2, &c2);
        sincosf(0.5f * qp[base + 3], &s3, &c3);
        float R0[2][2] = {{c0, -s0}, {s0, c0}};
        float R1[2][2] = {{c1, -s1}, {s1, c1}};
        float R2m[2][2] = {{c2, -s2}, {s2, c2}};
        float R3[2][2] = {{c3, -s3}, {s3, c3}};
        float A[4][4], G2m[4][4], Bm[4][4], Cm[4][4];
        #pragma unroll
        for (int ap = 0; ap < 2; ++ap)
        #pragma unroll
        for (int bp = 0; bp < 2; ++bp)
        #pragma unroll
        for (int aq = 0; aq < 2; ++aq)
        #pragma unroll
        for (int bq = 0; bq < 2; ++bq) {
            A[2 * ap + bp][2 * aq + bq]   = R0[ap][aq] * R1[bp][bq];
            G2m[2 * ap + bp][2 * aq + bq] = R2m[ap][aq] * R3[bp][bq];
        }
        const int sig1[4] = {0, 1, 3, 2};   // CNOT q1->q2
        const int sig2[4] = {0, 3, 2, 1};   // CNOT q2->q1
        #pragma unroll
        for (int xr = 0; xr < 4; ++xr)
            #pragma unroll
            for (int m = 0; m < 4; ++m) Bm[xr][m] = A[sig1[xr]][m];
        #pragma unroll
        for (int xr = 0; xr < 4; ++xr)
            #pragma unroll
            for (int m = 0; m < 4; ++m) {
                float acc = 0.f;
                #pragma unroll
                for (int y = 0; y < 4; ++y) acc = fmaf(G2m[xr][y], Bm[y][m], acc);
                Cm[xr][m] = acc;
            }
        #pragma unroll
        for (int xr = 0; xr < 4; ++xr)
            #pragma unroll
            for (int m = 0; m < 4; ++m) UUs[tid][xr * 4 + m] = Cm[sig2[xr]][m];
    }
    if (tid >= 16 && tid < 20) {
        float s, c;
        sincosf(0.5f * qp[56 + 2 * (tid - 16)], &s, &c);
        poolc[tid - 16] = c; pools[tid - 16] = s;
    }
    for (int i = tid; i < 512; i += 128) w1s[i] = w1[i];
    for (int i = tid; i < 2048; i += 128) {
        int row = i >> 6, j = i & 63;
        ((float*)w2p4)[row * 68 + j] = w2[i];
    }
    if (tid < 64) b1s[tid] = b1[tid];
    if (tid >= 64 && tid < 96) b2s[tid - 64] = b2[tid - 64];
    if (tid >= 96 && tid < 128) w3s[tid - 96] = w3[tid - 96];
    if (tid == 20) b3s = b3[0];
    __syncthreads();

    const int wid = tid >> 5;
    const int lane = tid & 31;
    const int ci = lane >> 3;                 // circuit-in-warp
    const int g = lane & 7;                   // lane-in-group
    const int cb = wid * 4 + ci;              // circuit-in-block
    const int cir = blockIdx.x * CPB + cb;
    const int b = cir / N_;
    const int n = cir - b * N_;

    // ---- angle projection: this lane computes angle q = g of its circuit ----
    float av;
    {
        av = b_proj[g];
        const float* wrow = w_proj + g * (S_ * F_);
        const float* xb = x + (size_t)b * (S_ * N_ * F_) + n * F_;
        #pragma unroll
        for (int s = 0; s < S_; ++s) {
            float2 xv = *(const float2*)(xb + s * (N_ * F_));
            av = fmaf(wrow[2 * s], xv.x, av);
            av = fmaf(wrow[2 * s + 1], xv.y, av);
        }
        av = fminf(fmaxf(av, -PI_F), PI_F);
    }
    float sv, cv;
    sincosf(0.5f * av, &sv, &cv);
    float ch[8], sh[8];
    #pragma unroll
    for (int q = 0; q < 8; ++q) {
        ch[q] = __shfl_sync(FULL, cv, (lane & 24) | q);
        sh[q] = __shfl_sync(FULL, sv, (lane & 24) | q);
    }

    // ---- initial product state + RZ phases ----
    const int b0 = (g >> 2) & 1, b4q = (g >> 1) & 1, b7q = g & 1;
    float magL = (b0 ? sh[0] : ch[0]) * (b4q ? sh[4] : ch[4]) * (b7q ? sh[7] : ch[7]);
    // phase factors: qubit i (0..3) gets RZ(a[4+i]); factor = ch[4+i] + i*(bit? sh : -sh)
    float fr = ch[4], fi = b0 ? sh[4] : -sh[4];
    float e1r[2], e1i[2];
    #pragma unroll
    for (int t = 0; t < 2; ++t) {
        float s1 = t ? sh[5] : -sh[5];
        e1r[t] = fmaf(fr, ch[5], -fi * s1);
        e1i[t] = fmaf(fr, s1, fi * ch[5]);
    }
    float e2r[4], e2i[4];
    #pragma unroll
    for (int t = 0; t < 4; ++t) {
        float s2 = (t & 1) ? sh[6] : -sh[6];
        e2r[t] = fmaf(e1r[t >> 1], ch[6], -e1i[t >> 1] * s2);
        e2i[t] = fmaf(e1r[t >> 1], s2, e1i[t >> 1] * ch[6]);
    }
    float wr[8], wi[8];
    #pragma unroll
    for (int t = 0; t < 8; ++t) {
        float s3 = (t & 1) ? sh[7] : -sh[7];
        float er = fmaf(e2r[t >> 1], ch[7], -e2i[t >> 1] * s3);
        float ei = fmaf(e2r[t >> 1], s3, e2i[t >> 1] * ch[7]);
        float mtop = ((t >> 2) ? sh[1] : ch[1]) * (((t >> 1) & 1) ? sh[2] : ch[2])
                   * ((t & 1) ? sh[3] : ch[3]);
        float w = magL * mtop;
        wr[t] = w * er;
        wi[t] = w * ei;
    }
    float ml[4];
    #pragma unroll
    for (int l = 0; l < 4; ++l)
        ml[l] = ((l >> 1) ? sh[5] : ch[5]) * ((l & 1) ? sh[6] : ch[6]);

    float re[32], im[32];
    #pragma unroll
    for (int r = 0; r < 32; ++r) {
        const int t = r >> 2, l = r & 3;
        re[r] = wr[t] * ml[l];
        im[r] = wi[t] * ml[l];
    }

    // ---- graph CNOTs: composed conditional XOR permutation ----
    const int c = n & 7;
    const int pcq = (0x50162347u >> (4 * c)) & 0xF;    // posOf[c]
    int cond = (adj[c * N_ + g] > 0.f) && (g != c);
    const unsigned bal = __ballot_sync(FULL, cond);
    const unsigned mask8 = (bal >> (ci * 8)) & 0xFFu;
    constexpr int posOf[8] = {7, 4, 3, 2, 6, 1, 0, 5};
    int M = 0;
    #pragma unroll
    for (int t = 0; t < 8; ++t) M |= (int)((mask8 >> t) & 1u) << posOf[t];
    const int glm = (M >> 5) & 7;
    const int MR = M & 31;
    const int jbase = g << 5;
    // lane pass
    #pragma unroll
    for (int r = 0; r < 32; ++r) {
        const int bc = ((jbase | r) >> pcq) & 1;
        const int src = (lane & 24) | (bc ? (g ^ glm) : g);
        re[r] = __shfl_sync(FULL, re[r], src);
        im[r] = __shfl_sync(FULL, im[r], src);
    }
    // register-bit passes (predicated swaps)
    #pragma unroll
    for (int t = 0; t < 5; ++t) {
        const int mt = 1 << t;
        const bool sw = (MR >> t) & 1;
        #pragma unroll
        for (int r0 = 0; r0 < 32; ++r0) if (!(r0 & mt)) {
            const int r1 = r0 | mt;
            const bool cnd = sw && (((jbase | r0) >> pcq) & 1);
            float t0 = re[r0], t1 = re[r1];
            re[r0] = cnd ? t1 : t0;  re[r1] = cnd ? t0 : t1;
            t0 = im[r0]; t1 = im[r1];
            im[r0] = cnd ? t1 : t0;  im[r1] = cnd ? t0 : t1;
        }
    }

    // ---- 2 conv layers ----
    #pragma unroll
    for (int l = 0; l < 2; ++l) {
        const float4* Ub = (const float4*)UUs[l * 7];
        conv_mx<2, 4, true>(re, im, Ub + 0 * 4, lane);    // (q0,q1)
        conv_rr<3, 2>(re, im, Ub + 1 * 4);                // (q2,q3)
        conv_mx<1, 1, true>(re, im, Ub + 2 * 4, lane);    // (q4,q5)
        conv_mx<0, 0, false>(re, im, Ub + 3 * 4, lane);   // (q6,q7)
        conv_rr<4, 3>(re, im, Ub + 4 * 4);                // (q1,q2)
        conv_mx<1, 2, false>(re, im, Ub + 5 * 4, lane);   // (q3,q4)
        conv_rr<1, 0>(re, im, Ub + 6 * 4);                // (q5,q6)
    }

    // ---- pooling RY on q0, q2, q4, q6 ----
    ry_lane<2>(re, im, poolc[0], pools[0], lane);  // q0
    ry_reg<3>(re, im, poolc[1], pools[1]);         // q2
    ry_lane<1>(re, im, poolc[2], pools[2], lane);  // q4
    ry_reg<0>(re, im, poolc[3], pools[3]);         // q6

    // ---- <Z_w> measurement ----
    float tot = 0.f, z1 = 0.f, z2 = 0.f, z3 = 0.f, z5 = 0.f, z6 = 0.f;
    #pragma unroll
    for (int r = 0; r < 32; ++r) {
        float p = fmaf(re[r], re[r], im[r] * im[r]);
        tot += p;
        z1 += ((r >> 4) & 1) ? -p : p;
        z2 += ((r >> 3) & 1) ? -p : p;
        z3 += ((r >> 2) & 1) ? -p : p;
        z5 += ((r >> 1) & 1) ? -p : p;
        z6 += (r & 1) ? -p : p;
    }
    float z[8];
    z[0] = b0 ? -tot : tot;
    z[4] = b4q ? -tot : tot;
    z[7] = b7q ? -tot : tot;
    z[1] = z1; z[2] = z2; z[3] = z3; z[5] = z5; z[6] = z6;
    #pragma unroll
    for (int off = 1; off < 8; off <<= 1) {
        #pragma unroll
        for (int w = 0; w < 8; ++w) z[w] += shx(z[w], off);
    }

    // ---- MLP head: 8 -> 64 -> 32 -> 1 ----
    // h1: this lane computes rows 8g .. 8g+7
    float h1v[8];
    const float* w1row = w1s + g * 64;
    #pragma unroll
    for (int i = 0; i < 8; ++i) {
        float4 wa = *(const float4*)(w1row + i * 8);
        float4 wb = *(const float4*)(w1row + i * 8 + 4);
        float acc = b1s[8 * g + i];
        acc = fmaf(wa.x, z[0], acc); acc = fmaf(wa.y, z[1], acc);
        acc = fmaf(wa.z, z[2], acc); acc = fmaf(wa.w, z[3], acc);
        acc = fmaf(wb.x, z[4], acc); acc = fmaf(wb.y, z[5], acc);
        acc = fmaf(wb.z, z[6], acc); acc = fmaf(wb.w, z[7], acc);
        h1v[i] = fmaxf(acc, 0.f);
    }
    {
        float4* dst = (float4*)((float*)h1buf4 + cb * 68 + 8 * g);
        dst[0] = make_float4(h1v[0], h1v[1], h1v[2], h1v[3]);
        dst[1] = make_float4(h1v[4], h1v[5], h1v[6], h1v[7]);
    }
    __syncwarp();

    // h2: this lane computes rows g, g+8, g+16, g+24
    float acc2[4];
    #pragma unroll
    for (int i = 0; i < 4; ++i) acc2[i] = b2s[g + 8 * i];
    const float4* h1p = h1buf4 + cb * 17;
    #pragma unroll
    for (int j4 = 0; j4 < 16; ++j4) {
        float4 h = h1p[j4];
        #pragma unroll
        for (int i = 0; i < 4; ++i) {
            float4 w = w2p4[(g + 8 * i) * 17 + j4];
            acc2[i] = fmaf(w.x, h.x, fmaf(w.y, h.y, fmaf(w.z, h.z, fmaf(w.w, h.w, acc2[i]))));
        }
    }
    float o = 0.f;
    #pragma unroll
    for (int i = 0; i < 4; ++i)
        o = fmaf(w3s[g + 8 * i], fmaxf(acc2[i], 0.f), o);
    o += shx(o, 1); o += shx(o, 2); o += shx(o, 4);
    if (g == 0) out[cir] = o + b3s;
}

extern "C" void kernel_launch(void* const* d_in, const int* in_sizes, int n_in,
                              void* d_out, int out_size) {
    const float* x      = (const float*)d_in[0];
    const float* adj    = (const float*)d_in[1];
    const float* w_proj = (const float*)d_in[2];
    const float* b_proj = (const float*)d_in[3];
    const float* qp     = (const float*)d_in[4];
    const float* w1     = (const float*)d_in[5];
    const float* b1     = (const float*)d_in[6];
    const float* w2     = (const float*)d_in[7];
    const float* b2     = (const float*)d_in[8];
    const float* w3     = (const float*)d_in[9];
    const float* b3     = (const float*)d_in[10];
    float* out = (float*)d_out;

    const int blocks = NCIRC / CPB;   // 828
    qcnn_kernel<<<blocks, 128>>>(x, adj, w_proj, b_proj, qp,
                                 w1, b1, w2, b2, w3, b3, out);
}